// round 13
// baseline (speedup 1.0000x reference)
#include <cuda_runtime.h>
#include <cuda_fp16.h>

#define N_NODES 50000
#define E_EDGES 800000
#define TOT_E   (E_EDGES + N_NODES)   // 850000, incl. self-loops
#define HID     32
#define HEADS   4
#define F1      (HEADS * HID)          // 128
#define NEG_SLOPE 0.2f

#define SCAN_CHUNK 512
#define NB_SCAN    ((N_NODES + SCAN_CHUNK - 1) / SCAN_CHUNK)   // 98

// ---- scratch (device globals; no allocation allowed) ----
__device__ int   g_cnt[N_NODES];
__device__ int   g_off[N_NODES];
__device__ int   g_total;
__device__ int   g_rank[TOT_E];
__device__ int   g_csr[TOT_E];
__device__ __align__(16) __half g_h1h[N_NODES * F1];   // layer1 feats fp16
__device__ __align__(16) float  g_as1[N_NODES * HEADS];
__device__ __align__(16) float  g_ad1[N_NODES * HEADS];
__device__ __align__(16) float  g_out1[N_NODES * F1];  // post-softmax, post-ELU
__device__ __align__(16) float  g_h2[N_NODES * HID];   // layer2 feats fp32
__device__ float g_as2[N_NODES];
__device__ float g_ad2[N_NODES];

__device__ __forceinline__ float warp_sum_f(float v) {
#pragma unroll
    for (int o = 16; o; o >>= 1) v += __shfl_xor_sync(0xffffffffu, v, o);
    return v;
}
__device__ __forceinline__ float lrelu(float e) { return e > 0.f ? e : NEG_SLOPE * e; }
__device__ __forceinline__ float elu(float v)   { return v > 0.f ? v : __expf(v) - 1.f; }

// ============================================================================
// K1: h1 = x @ W1 (fp16); attention scalars via a = x·(W1@attᵀ).
// Also zeros g_cnt and g_total.
// ============================================================================
__global__ void k1_node1(const float* __restrict__ x,  const float* __restrict__ W1,
                         const float* __restrict__ as1, const float* __restrict__ ad1) {
    __shared__ float sW[5 * F1];
    __shared__ float sva[5 * HEADS], svb[5 * HEADS];
    int t = threadIdx.x;
    int n0 = blockIdx.x * 32;
    if (t < 32 && n0 + t < N_NODES) g_cnt[n0 + t] = 0;
    if (blockIdx.x == 0 && t == 32) g_total = 0;

    for (int i = t; i < 5 * F1; i += 128) sW[i] = W1[i];
    if (t < 5 * HEADS) {
        int k = t / HEADS, h = t % HEADS;
        float s = 0.f, d = 0.f;
        for (int c = 0; c < HID; c++) {
            float w = W1[k * F1 + h * HID + c];
            s = fmaf(w, as1[h * HID + c], s);
            d = fmaf(w, ad1[h * HID + c], d);
        }
        sva[t] = s; svb[t] = d;
    }
    __syncthreads();

    for (int j = 0; j < 32; j++) {
        int n = n0 + j;
        if (n >= N_NODES) return;
        float xv[5];
#pragma unroll
        for (int k = 0; k < 5; k++) xv[k] = x[n * 5 + k];
        float h = 0.f;
#pragma unroll
        for (int k = 0; k < 5; k++) h = fmaf(xv[k], sW[k * F1 + t], h);
        g_h1h[n * F1 + t] = __float2half_rn(h);
        if (t < HEADS) {
            float s = 0.f, d = 0.f;
#pragma unroll
            for (int k = 0; k < 5; k++) {
                s = fmaf(xv[k], sva[k * HEADS + t], s);
                d = fmaf(xv[k], svb[k * HEADS + t], d);
            }
            g_as1[n * HEADS + t] = s;
            g_ad1[n * HEADS + t] = d;
        }
    }
}

// ============================================================================
// kH: histogram + per-edge rank (atomicAdd return). 4 striped edges/thread.
// ============================================================================
#define EB 4
#define KH_T ((TOT_E + EB - 1) / EB)
__global__ void kH(const int* __restrict__ ei) {
    int gid = blockIdx.x * blockDim.x + threadIdx.x;
    if (gid >= KH_T) return;
#pragma unroll
    for (int i = 0; i < EB; i++) {
        int e = gid + i * KH_T;
        if (e < TOT_E) {
            int dst = (e < E_EDGES) ? ei[E_EDGES + e] : (e - E_EDGES);
            g_rank[e] = atomicAdd(&g_cnt[dst], 1);
        }
    }
}

// ============================================================================
// kOff: block scan + one atomicAdd base claim
// ============================================================================
__global__ void kOff() {
    __shared__ int ws[SCAN_CHUNK / 32 + 1];
    __shared__ int sbase;
    int t = threadIdx.x, b = blockIdx.x;
    int i = b * SCAN_CHUNK + t;
    int lane = t & 31, wid = t >> 5;

    int v = (i < N_NODES) ? g_cnt[i] : 0;
    int x = v;
#pragma unroll
    for (int o = 1; o < 32; o <<= 1) {
        int y = __shfl_up_sync(0xffffffffu, x, o);
        if (lane >= o) x += y;
    }
    if (lane == 31) ws[wid + 1] = x;
    __syncthreads();
    if (t == 0) {
        ws[0] = 0;
        for (int w = 1; w <= SCAN_CHUNK / 32; w++) ws[w] += ws[w - 1];
        sbase = atomicAdd(&g_total, ws[SCAN_CHUNK / 32]);
    }
    __syncthreads();
    int excl = x - v + ws[wid] + sbase;
    if (i < N_NODES) g_off[i] = excl;
}

// ============================================================================
// kC: atomic-free scatter via precomputed ranks
// ============================================================================
__global__ void kC(const int* __restrict__ ei) {
    int e = blockIdx.x * blockDim.x + threadIdx.x;
    if (e >= TOT_E) return;
    int src, dst;
    if (e < E_EDGES) { src = ei[e]; dst = ei[E_EDGES + e]; }
    else             { src = dst = e - E_EDGES; }
    g_csr[g_off[dst] + g_rank[e]] = src;
}

// ============================================================================
// KG1: layer-1 gather — TWO warps per node, each walks half the edge list
// (4-wide), partials combined in smem. 256 thr = 8 warps = 4 nodes/block.
// 100K warps total; serial chain per warp halved.
// ============================================================================
__global__ void kG1(const float* __restrict__ b1) {
    __shared__ float sP[8][4][32];      // [warp][feat-quad][lane] — conflict-free
    __shared__ float sD[8][32];
    int t = threadIdx.x;
    int wid = t >> 5, lane = t & 31;
    int half = wid & 1;
    int n = blockIdx.x * 4 + (wid >> 1);
    bool active = (n < N_NODES);
    int head = lane >> 3;
    int f = lane * 4;

    float a0 = 0.f, a1 = 0.f, a2 = 0.f, a3 = 0.f, den = 0.f;
    if (active) {
        float adv = g_ad1[n * HEADS + head];
        int beg = g_off[n], cnt = g_cnt[n];
        int mid = cnt >> 1;
        int j    = half ? mid : 0;
        int jend = half ? cnt : mid;

        for (; j + 3 < jend; j += 4) {
            int s0 = g_csr[beg + j + 0];
            int s1 = g_csr[beg + j + 1];
            int s2 = g_csr[beg + j + 2];
            int s3 = g_csr[beg + j + 3];
            float e0 = g_as1[s0 * HEADS + head];
            float e1 = g_as1[s1 * HEADS + head];
            float e2 = g_as1[s2 * HEADS + head];
            float e3 = g_as1[s3 * HEADS + head];
            uint2 r0 = *reinterpret_cast<const uint2*>(&g_h1h[s0 * F1 + f]);
            uint2 r1 = *reinterpret_cast<const uint2*>(&g_h1h[s1 * F1 + f]);
            uint2 r2 = *reinterpret_cast<const uint2*>(&g_h1h[s2 * F1 + f]);
            uint2 r3 = *reinterpret_cast<const uint2*>(&g_h1h[s3 * F1 + f]);
            float w0 = __expf(lrelu(e0 + adv));
            float w1 = __expf(lrelu(e1 + adv));
            float w2 = __expf(lrelu(e2 + adv));
            float w3 = __expf(lrelu(e3 + adv));
            float2 pa, pb;
            pa = __half22float2(*reinterpret_cast<__half2*>(&r0.x));
            pb = __half22float2(*reinterpret_cast<__half2*>(&r0.y));
            a0 = fmaf(w0, pa.x, a0); a1 = fmaf(w0, pa.y, a1);
            a2 = fmaf(w0, pb.x, a2); a3 = fmaf(w0, pb.y, a3);
            pa = __half22float2(*reinterpret_cast<__half2*>(&r1.x));
            pb = __half22float2(*reinterpret_cast<__half2*>(&r1.y));
            a0 = fmaf(w1, pa.x, a0); a1 = fmaf(w1, pa.y, a1);
            a2 = fmaf(w1, pb.x, a2); a3 = fmaf(w1, pb.y, a3);
            pa = __half22float2(*reinterpret_cast<__half2*>(&r2.x));
            pb = __half22float2(*reinterpret_cast<__half2*>(&r2.y));
            a0 = fmaf(w2, pa.x, a0); a1 = fmaf(w2, pa.y, a1);
            a2 = fmaf(w2, pb.x, a2); a3 = fmaf(w2, pb.y, a3);
            pa = __half22float2(*reinterpret_cast<__half2*>(&r3.x));
            pb = __half22float2(*reinterpret_cast<__half2*>(&r3.y));
            a0 = fmaf(w3, pa.x, a0); a1 = fmaf(w3, pa.y, a1);
            a2 = fmaf(w3, pb.x, a2); a3 = fmaf(w3, pb.y, a3);
            den += (w0 + w1) + (w2 + w3);
        }
        for (; j < jend; j++) {
            int s0 = g_csr[beg + j];
            float e0 = g_as1[s0 * HEADS + head];
            uint2 r0 = *reinterpret_cast<const uint2*>(&g_h1h[s0 * F1 + f]);
            float w0 = __expf(lrelu(e0 + adv));
            float2 pa = __half22float2(*reinterpret_cast<__half2*>(&r0.x));
            float2 pb = __half22float2(*reinterpret_cast<__half2*>(&r0.y));
            a0 = fmaf(w0, pa.x, a0); a1 = fmaf(w0, pa.y, a1);
            a2 = fmaf(w0, pb.x, a2); a3 = fmaf(w0, pb.y, a3);
            den += w0;
        }
    }
    sP[wid][0][lane] = a0;
    sP[wid][1][lane] = a1;
    sP[wid][2][lane] = a2;
    sP[wid][3][lane] = a3;
    sD[wid][lane] = den;
    __syncthreads();

    if (half == 0 && active) {
        a0 += sP[wid + 1][0][lane];
        a1 += sP[wid + 1][1][lane];
        a2 += sP[wid + 1][2][lane];
        a3 += sP[wid + 1][3][lane];
        den += sD[wid + 1][lane];
        float inv = 1.f / den;
        float4 bv = *reinterpret_cast<const float4*>(&b1[f]);
        float4 o;
        o.x = elu(fmaf(a0, inv, bv.x));
        o.y = elu(fmaf(a1, inv, bv.y));
        o.z = elu(fmaf(a2, inv, bv.z));
        o.w = elu(fmaf(a3, inv, bv.w));
        *reinterpret_cast<float4*>(&g_out1[n * F1 + f]) = o;
    }
}

// ============================================================================
// K3: h2 = out1 @ W2, register-blocked 4 nodes/warp
// ============================================================================
__global__ void k3_node2(const float* __restrict__ W2,
                         const float* __restrict__ as2, const float* __restrict__ ad2) {
    __shared__ float sW2[F1 * HID];
    __shared__ float sH[8][4][F1];
    int t = threadIdx.x;
    for (int i = t; i < F1 * HID; i += 256) sW2[i] = W2[i];
    __syncthreads();

    int wid = t >> 5, lane = t & 31;
    int n0 = blockIdx.x * 32 + wid * 4;

#pragma unroll
    for (int j = 0; j < 4; j++) {
        int n = n0 + j;
        if (n < N_NODES) {
#pragma unroll
            for (int q = 0; q < 4; q++)
                sH[wid][j][q * 32 + lane] = g_out1[n * F1 + q * 32 + lane];
        }
    }
    __syncwarp();

    float acc0 = 0.f, acc1 = 0.f, acc2 = 0.f, acc3 = 0.f;
#pragma unroll 4
    for (int k = 0; k < F1; k++) {
        float w = sW2[k * HID + lane];
        acc0 = fmaf(sH[wid][0][k], w, acc0);
        acc1 = fmaf(sH[wid][1][k], w, acc1);
        acc2 = fmaf(sH[wid][2][k], w, acc2);
        acc3 = fmaf(sH[wid][3][k], w, acc3);
    }

    float accs[4] = {acc0, acc1, acc2, acc3};
#pragma unroll
    for (int j = 0; j < 4; j++) {
        int n = n0 + j;
        float acc = accs[j];
        float ps = warp_sum_f(acc * as2[lane]);
        float pd = warp_sum_f(acc * ad2[lane]);
        if (n < N_NODES) {
            g_h2[n * HID + lane] = acc;
            if (lane == 0) { g_as2[n] = ps; g_ad2[n] = pd; }
        }
    }
}

// ============================================================================
// KG2: layer-2 gather + MLP head — TWO warps per node, half the edges each,
// partials combined in smem. 8 warps = 4 nodes per 256-thread block.
// ============================================================================
__global__ void kG2(const float* __restrict__ b2,  const float* __restrict__ Wc1,
                    const float* __restrict__ bc1, const float* __restrict__ Wc2,
                    const float* __restrict__ bc2, float* __restrict__ out) {
    __shared__ float sAcc[8][32];
    __shared__ float sDen[8];
    __shared__ float sv[4][HID];
    int t = threadIdx.x;
    int wid = t >> 5, lane = t & 31;
    int half = wid & 1;
    int slot = wid >> 1;                 // node slot 0..3
    int n = blockIdx.x * 4 + slot;
    bool active = (n < N_NODES);

    float acc = 0.f, den = 0.f;
    if (active) {
        float adv = g_ad2[n];
        int beg = g_off[n], cnt = g_cnt[n];
        int mid = cnt >> 1;
        int j    = half ? mid : 0;
        int jend = half ? cnt : mid;

        for (; j + 3 < jend; j += 4) {
            int s0 = g_csr[beg + j + 0];
            int s1 = g_csr[beg + j + 1];
            int s2 = g_csr[beg + j + 2];
            int s3 = g_csr[beg + j + 3];
            float e0 = g_as2[s0];
            float e1 = g_as2[s1];
            float e2 = g_as2[s2];
            float e3 = g_as2[s3];
            float h0 = g_h2[s0 * HID + lane];
            float h1 = g_h2[s1 * HID + lane];
            float h2v = g_h2[s2 * HID + lane];
            float h3 = g_h2[s3 * HID + lane];
            float w0 = __expf(lrelu(e0 + adv));
            float w1 = __expf(lrelu(e1 + adv));
            float w2 = __expf(lrelu(e2 + adv));
            float w3 = __expf(lrelu(e3 + adv));
            acc = fmaf(w0, h0, acc);
            acc = fmaf(w1, h1, acc);
            acc = fmaf(w2, h2v, acc);
            acc = fmaf(w3, h3, acc);
            den += (w0 + w1) + (w2 + w3);
        }
        for (; j < jend; j++) {
            int s0 = g_csr[beg + j];
            float w0 = __expf(lrelu(g_as2[s0] + adv));
            acc = fmaf(w0, g_h2[s0 * HID + lane], acc);
            den += w0;
        }
    }
    sAcc[wid][lane] = acc;
    if (lane == 0) sDen[wid] = den;     // den is lane-uniform in layer 2
    __syncthreads();

    if (half == 0 && active) {
        acc += sAcc[wid + 1][lane];
        den += sDen[wid + 1];
        float v = elu(acc / den + b2[lane]);
        sv[slot][lane] = v;
        __syncwarp();

        float tj = 0.f;
        if (lane < 16) {
            tj = bc1[lane];
#pragma unroll
            for (int c = 0; c < HID; c++) tj = fmaf(sv[slot][c], Wc1[c * 16 + lane], tj);
            tj = fmaxf(tj, 0.f) * Wc2[lane];
        }
#pragma unroll
        for (int o = 16; o; o >>= 1) tj += __shfl_xor_sync(0xffffffffu, tj, o);
        if (lane == 0) out[n] = tj + bc2[0];
    }
}

// ============================================================================
extern "C" void kernel_launch(void* const* d_in, const int* in_sizes, int n_in,
                              void* d_out, int out_size) {
    const float* x   = (const float*)d_in[0];
    const int*   ei  = (const int*)  d_in[1];
    const float* W1  = (const float*)d_in[2];
    const float* as1 = (const float*)d_in[3];
    const float* ad1 = (const float*)d_in[4];
    const float* b1  = (const float*)d_in[5];
    const float* W2  = (const float*)d_in[6];
    const float* as2 = (const float*)d_in[7];
    const float* ad2 = (const float*)d_in[8];
    const float* b2  = (const float*)d_in[9];
    const float* Wc1 = (const float*)d_in[10];
    const float* bc1 = (const float*)d_in[11];
    const float* Wc2 = (const float*)d_in[12];
    const float* bc2 = (const float*)d_in[13];
    float* out = (float*)d_out;

    k1_node1<<<(N_NODES + 31) / 32, 128>>>(x, W1, as1, ad1);
    kH  <<<(KH_T + 255) / 256, 256>>>(ei);
    kOff<<<NB_SCAN, SCAN_CHUNK>>>();
    kC  <<<(TOT_E + 255) / 256, 256>>>(ei);
    kG1 <<<(N_NODES + 3) / 4, 256>>>(b1);                      // 2 warps/node
    k3_node2<<<(N_NODES + 31) / 32, 256>>>(W2, as2, ad2);
    kG2 <<<(N_NODES + 3) / 4, 256>>>(b2, Wc1, bc1, Wc2, bc2, out);
}

// round 14
// speedup vs baseline: 1.1213x; 1.1213x over previous
#include <cuda_runtime.h>
#include <cuda_fp16.h>

#define N_NODES 50000
#define E_EDGES 800000
#define TOT_E   (E_EDGES + N_NODES)   // 850000, incl. self-loops
#define HID     32
#define HEADS   4
#define F1      (HEADS * HID)          // 128
#define NEG_SLOPE 0.2f

#define SCAN_CHUNK 512
#define NB_SCAN    ((N_NODES + SCAN_CHUNK - 1) / SCAN_CHUNK)   // 98
#define NB_K1      ((N_NODES + 31) / 32)                       // 1563 dense blocks
#define NB_KH      ((TOT_E + 127) / 128)                       // 6641 histo blocks

// ---- scratch (device globals; no allocation allowed) ----
__device__ int   g_cnt[N_NODES];
__device__ int   g_off[N_NODES];
__device__ int   g_total;
__device__ int   g_rank[TOT_E];
__device__ int   g_csr[TOT_E];
__device__ __align__(16) __half g_h1h[N_NODES * F1];   // layer1 feats fp16
__device__ __align__(16) float  g_as1[N_NODES * HEADS];
__device__ __align__(16) float  g_ad1[N_NODES * HEADS];
__device__ __align__(16) float  g_out1[N_NODES * F1];  // post-softmax, post-ELU
__device__ __align__(16) float  g_h2[N_NODES * HID];   // layer2 feats fp32
__device__ float g_as2[N_NODES];
__device__ float g_ad2[N_NODES];

__device__ __forceinline__ float warp_sum_f(float v) {
#pragma unroll
    for (int o = 16; o; o >>= 1) v += __shfl_xor_sync(0xffffffffu, v, o);
    return v;
}
__device__ __forceinline__ float lrelu(float e) { return e > 0.f ? e : NEG_SLOPE * e; }
__device__ __forceinline__ float elu(float v)   { return v > 0.f ? v : __expf(v) - 1.f; }

// ============================================================================
// kZ: zero degree counters + global cursor (must precede kF's histogram half)
// ============================================================================
__global__ void kZ() {
    int i = blockIdx.x * blockDim.x + threadIdx.x;
    if (i < N_NODES) g_cnt[i] = 0;
    if (i == 0) g_total = 0;
}

// ============================================================================
// kF: FUSED dense transform + histogram. Blocks [0,NB_K1) compute
// h1 = x@W1 (fp16) + attention scalars; blocks [NB_K1, NB_K1+NB_KH) do the
// dst histogram + per-edge rank. The halves touch disjoint state, so they
// need no ordering and overlap on the SMs (saves serializing k1 before kH).
// 128 threads/block.
// ============================================================================
__global__ void kF(const float* __restrict__ x,  const float* __restrict__ W1,
                   const float* __restrict__ as1, const float* __restrict__ ad1,
                   const int* __restrict__ ei) {
    if (blockIdx.x >= NB_K1) {
        // ---- histogram half: 1 edge/thread, full TLP ----
        int e = (blockIdx.x - NB_K1) * 128 + threadIdx.x;
        if (e < TOT_E) {
            int dst = (e < E_EDGES) ? ei[E_EDGES + e] : (e - E_EDGES);
            g_rank[e] = atomicAdd(&g_cnt[dst], 1);
        }
        return;
    }

    // ---- dense half: 32 nodes/block ----
    __shared__ float sW[5 * F1];
    __shared__ float sva[5 * HEADS], svb[5 * HEADS];
    int t = threadIdx.x;
    int n0 = blockIdx.x * 32;

    for (int i = t; i < 5 * F1; i += 128) sW[i] = W1[i];
    if (t < 5 * HEADS) {
        int k = t / HEADS, h = t % HEADS;
        float s = 0.f, d = 0.f;
        for (int c = 0; c < HID; c++) {
            float w = W1[k * F1 + h * HID + c];
            s = fmaf(w, as1[h * HID + c], s);
            d = fmaf(w, ad1[h * HID + c], d);
        }
        sva[t] = s; svb[t] = d;
    }
    __syncthreads();

    for (int j = 0; j < 32; j++) {
        int n = n0 + j;
        if (n >= N_NODES) return;
        float xv[5];
#pragma unroll
        for (int k = 0; k < 5; k++) xv[k] = x[n * 5 + k];
        float h = 0.f;
#pragma unroll
        for (int k = 0; k < 5; k++) h = fmaf(xv[k], sW[k * F1 + t], h);
        g_h1h[n * F1 + t] = __float2half_rn(h);
        if (t < HEADS) {
            float s = 0.f, d = 0.f;
#pragma unroll
            for (int k = 0; k < 5; k++) {
                s = fmaf(xv[k], sva[k * HEADS + t], s);
                d = fmaf(xv[k], svb[k * HEADS + t], d);
            }
            g_as1[n * HEADS + t] = s;
            g_ad1[n * HEADS + t] = d;
        }
    }
}

// ============================================================================
// kOff: block scan + one atomicAdd base claim
// ============================================================================
__global__ void kOff() {
    __shared__ int ws[SCAN_CHUNK / 32 + 1];
    __shared__ int sbase;
    int t = threadIdx.x, b = blockIdx.x;
    int i = b * SCAN_CHUNK + t;
    int lane = t & 31, wid = t >> 5;

    int v = (i < N_NODES) ? g_cnt[i] : 0;
    int x = v;
#pragma unroll
    for (int o = 1; o < 32; o <<= 1) {
        int y = __shfl_up_sync(0xffffffffu, x, o);
        if (lane >= o) x += y;
    }
    if (lane == 31) ws[wid + 1] = x;
    __syncthreads();
    if (t == 0) {
        ws[0] = 0;
        for (int w = 1; w <= SCAN_CHUNK / 32; w++) ws[w] += ws[w - 1];
        sbase = atomicAdd(&g_total, ws[SCAN_CHUNK / 32]);
    }
    __syncthreads();
    int excl = x - v + ws[wid] + sbase;
    if (i < N_NODES) g_off[i] = excl;
}

// ============================================================================
// kC: atomic-free scatter via precomputed ranks (1 edge/thread, full TLP)
// ============================================================================
__global__ void kC(const int* __restrict__ ei) {
    int e = blockIdx.x * blockDim.x + threadIdx.x;
    if (e >= TOT_E) return;
    int src, dst;
    if (e < E_EDGES) { src = ei[e]; dst = ei[E_EDGES + e]; }
    else             { src = dst = e - E_EDGES; }
    g_csr[g_off[dst] + g_rank[e]] = src;
}

// ============================================================================
// KG1: layer-1 gather (fp16 feats). R12 form: ONE warp/node, uncoupled,
// 4-wide unroll (validated optimum).
// ============================================================================
__global__ void kG1(const float* __restrict__ b1) {
    int n = (blockIdx.x * blockDim.x + threadIdx.x) >> 5;
    if (n >= N_NODES) return;
    int lane = threadIdx.x & 31;
    int head = lane >> 3;
    int f = lane * 4;

    float adv = g_ad1[n * HEADS + head];
    int beg = g_off[n], cnt = g_cnt[n];

    float a0 = 0.f, a1 = 0.f, a2 = 0.f, a3 = 0.f, den = 0.f;
    int j = 0;
    for (; j + 3 < cnt; j += 4) {
        int s0 = g_csr[beg + j + 0];
        int s1 = g_csr[beg + j + 1];
        int s2 = g_csr[beg + j + 2];
        int s3 = g_csr[beg + j + 3];
        float e0 = g_as1[s0 * HEADS + head];
        float e1 = g_as1[s1 * HEADS + head];
        float e2 = g_as1[s2 * HEADS + head];
        float e3 = g_as1[s3 * HEADS + head];
        uint2 r0 = *reinterpret_cast<const uint2*>(&g_h1h[s0 * F1 + f]);
        uint2 r1 = *reinterpret_cast<const uint2*>(&g_h1h[s1 * F1 + f]);
        uint2 r2 = *reinterpret_cast<const uint2*>(&g_h1h[s2 * F1 + f]);
        uint2 r3 = *reinterpret_cast<const uint2*>(&g_h1h[s3 * F1 + f]);
        float w0 = __expf(lrelu(e0 + adv));
        float w1 = __expf(lrelu(e1 + adv));
        float w2 = __expf(lrelu(e2 + adv));
        float w3 = __expf(lrelu(e3 + adv));
        float2 pa, pb;
        pa = __half22float2(*reinterpret_cast<__half2*>(&r0.x));
        pb = __half22float2(*reinterpret_cast<__half2*>(&r0.y));
        a0 = fmaf(w0, pa.x, a0); a1 = fmaf(w0, pa.y, a1);
        a2 = fmaf(w0, pb.x, a2); a3 = fmaf(w0, pb.y, a3);
        pa = __half22float2(*reinterpret_cast<__half2*>(&r1.x));
        pb = __half22float2(*reinterpret_cast<__half2*>(&r1.y));
        a0 = fmaf(w1, pa.x, a0); a1 = fmaf(w1, pa.y, a1);
        a2 = fmaf(w1, pb.x, a2); a3 = fmaf(w1, pb.y, a3);
        pa = __half22float2(*reinterpret_cast<__half2*>(&r2.x));
        pb = __half22float2(*reinterpret_cast<__half2*>(&r2.y));
        a0 = fmaf(w2, pa.x, a0); a1 = fmaf(w2, pa.y, a1);
        a2 = fmaf(w2, pb.x, a2); a3 = fmaf(w2, pb.y, a3);
        pa = __half22float2(*reinterpret_cast<__half2*>(&r3.x));
        pb = __half22float2(*reinterpret_cast<__half2*>(&r3.y));
        a0 = fmaf(w3, pa.x, a0); a1 = fmaf(w3, pa.y, a1);
        a2 = fmaf(w3, pb.x, a2); a3 = fmaf(w3, pb.y, a3);
        den += (w0 + w1) + (w2 + w3);
    }
    for (; j < cnt; j++) {
        int s0 = g_csr[beg + j];
        float e0 = g_as1[s0 * HEADS + head];
        uint2 r0 = *reinterpret_cast<const uint2*>(&g_h1h[s0 * F1 + f]);
        float w0 = __expf(lrelu(e0 + adv));
        float2 pa = __half22float2(*reinterpret_cast<__half2*>(&r0.x));
        float2 pb = __half22float2(*reinterpret_cast<__half2*>(&r0.y));
        a0 = fmaf(w0, pa.x, a0); a1 = fmaf(w0, pa.y, a1);
        a2 = fmaf(w0, pb.x, a2); a3 = fmaf(w0, pb.y, a3);
        den += w0;
    }
    float inv = 1.f / den;
    float4 bv = *reinterpret_cast<const float4*>(&b1[f]);
    float4 o;
    o.x = elu(fmaf(a0, inv, bv.x));
    o.y = elu(fmaf(a1, inv, bv.y));
    o.z = elu(fmaf(a2, inv, bv.z));
    o.w = elu(fmaf(a3, inv, bv.w));
    *reinterpret_cast<float4*>(&g_out1[n * F1 + f]) = o;
}

// ============================================================================
// K3: h2 = out1 @ W2, register-blocked 4 nodes/warp
// ============================================================================
__global__ void k3_node2(const float* __restrict__ W2,
                         const float* __restrict__ as2, const float* __restrict__ ad2) {
    __shared__ float sW2[F1 * HID];
    __shared__ float sH[8][4][F1];
    int t = threadIdx.x;
    for (int i = t; i < F1 * HID; i += 256) sW2[i] = W2[i];
    __syncthreads();

    int wid = t >> 5, lane = t & 31;
    int n0 = blockIdx.x * 32 + wid * 4;

#pragma unroll
    for (int j = 0; j < 4; j++) {
        int n = n0 + j;
        if (n < N_NODES) {
#pragma unroll
            for (int q = 0; q < 4; q++)
                sH[wid][j][q * 32 + lane] = g_out1[n * F1 + q * 32 + lane];
        }
    }
    __syncwarp();

    float acc0 = 0.f, acc1 = 0.f, acc2 = 0.f, acc3 = 0.f;
#pragma unroll 4
    for (int k = 0; k < F1; k++) {
        float w = sW2[k * HID + lane];
        acc0 = fmaf(sH[wid][0][k], w, acc0);
        acc1 = fmaf(sH[wid][1][k], w, acc1);
        acc2 = fmaf(sH[wid][2][k], w, acc2);
        acc3 = fmaf(sH[wid][3][k], w, acc3);
    }

    float accs[4] = {acc0, acc1, acc2, acc3};
#pragma unroll
    for (int j = 0; j < 4; j++) {
        int n = n0 + j;
        float acc = accs[j];
        float ps = warp_sum_f(acc * as2[lane]);
        float pd = warp_sum_f(acc * ad2[lane]);
        if (n < N_NODES) {
            g_h2[n * HID + lane] = acc;
            if (lane == 0) { g_as2[n] = ps; g_ad2[n] = pd; }
        }
    }
}

// ============================================================================
// KG2: layer-2 gather (fp32) + fused MLP head. R12 form: one warp/node, 4-wide.
// ============================================================================
__global__ void kG2(const float* __restrict__ b2,  const float* __restrict__ Wc1,
                    const float* __restrict__ bc1, const float* __restrict__ Wc2,
                    const float* __restrict__ bc2, float* __restrict__ out) {
    __shared__ float sv[8][HID];
    int n = (blockIdx.x * blockDim.x + threadIdx.x) >> 5;
    if (n >= N_NODES) return;
    int lane = threadIdx.x & 31;
    int wid = (threadIdx.x >> 5) & 7;

    float adv = g_ad2[n];
    int beg = g_off[n], cnt = g_cnt[n];

    float acc = 0.f, den = 0.f;
    int j = 0;
    for (; j + 3 < cnt; j += 4) {
        int s0 = g_csr[beg + j + 0];
        int s1 = g_csr[beg + j + 1];
        int s2 = g_csr[beg + j + 2];
        int s3 = g_csr[beg + j + 3];
        float e0 = g_as2[s0];
        float e1 = g_as2[s1];
        float e2 = g_as2[s2];
        float e3 = g_as2[s3];
        float h0 = g_h2[s0 * HID + lane];
        float h1 = g_h2[s1 * HID + lane];
        float h2v = g_h2[s2 * HID + lane];
        float h3 = g_h2[s3 * HID + lane];
        float w0 = __expf(lrelu(e0 + adv));
        float w1 = __expf(lrelu(e1 + adv));
        float w2 = __expf(lrelu(e2 + adv));
        float w3 = __expf(lrelu(e3 + adv));
        acc = fmaf(w0, h0, acc);
        acc = fmaf(w1, h1, acc);
        acc = fmaf(w2, h2v, acc);
        acc = fmaf(w3, h3, acc);
        den += (w0 + w1) + (w2 + w3);
    }
    for (; j < cnt; j++) {
        int s0 = g_csr[beg + j];
        float w0 = __expf(lrelu(g_as2[s0] + adv));
        acc = fmaf(w0, g_h2[s0 * HID + lane], acc);
        den += w0;
    }
    float v = elu(acc / den + b2[lane]);
    sv[wid][lane] = v;
    __syncwarp();

    float tj = 0.f;
    if (lane < 16) {
        tj = bc1[lane];
#pragma unroll
        for (int c = 0; c < HID; c++) tj = fmaf(sv[wid][c], Wc1[c * 16 + lane], tj);
        tj = fmaxf(tj, 0.f) * Wc2[lane];
    }
#pragma unroll
    for (int o = 16; o; o >>= 1) tj += __shfl_xor_sync(0xffffffffu, tj, o);
    if (lane == 0) out[n] = tj + bc2[0];
}

// ============================================================================
extern "C" void kernel_launch(void* const* d_in, const int* in_sizes, int n_in,
                              void* d_out, int out_size) {
    const float* x   = (const float*)d_in[0];
    const int*   ei  = (const int*)  d_in[1];
    const float* W1  = (const float*)d_in[2];
    const float* as1 = (const float*)d_in[3];
    const float* ad1 = (const float*)d_in[4];
    const float* b1  = (const float*)d_in[5];
    const float* W2  = (const float*)d_in[6];
    const float* as2 = (const float*)d_in[7];
    const float* ad2 = (const float*)d_in[8];
    const float* b2  = (const float*)d_in[9];
    const float* Wc1 = (const float*)d_in[10];
    const float* bc1 = (const float*)d_in[11];
    const float* Wc2 = (const float*)d_in[12];
    const float* bc2 = (const float*)d_in[13];
    float* out = (float*)d_out;

    kZ  <<<(N_NODES + 255) / 256, 256>>>();
    kF  <<<NB_K1 + NB_KH, 128>>>(x, W1, as1, ad1, ei);         // k1 ∥ kH overlapped
    kOff<<<NB_SCAN, SCAN_CHUNK>>>();
    kC  <<<(TOT_E + 255) / 256, 256>>>(ei);
    kG1 <<<(N_NODES * 32 + 255) / 256, 256>>>(b1);             // R12 gather shape
    k3_node2<<<(N_NODES + 31) / 32, 256>>>(W2, as2, ad2);
    kG2 <<<(N_NODES * 32 + 255) / 256, 256>>>(b2, Wc1, bc1, Wc2, bc2, out);
}

// round 15
// speedup vs baseline: 1.1312x; 1.0088x over previous
#include <cuda_runtime.h>
#include <cuda_fp16.h>

#define N_NODES 50000
#define E_EDGES 800000
#define TOT_E   (E_EDGES + N_NODES)   // 850000, incl. self-loops
#define HID     32
#define HEADS   4
#define F1      (HEADS * HID)          // 128
#define NEG_SLOPE 0.2f

#define SCAN_CHUNK 512
#define NB_SCAN    ((N_NODES + SCAN_CHUNK - 1) / SCAN_CHUNK)   // 98
#define NB_K1      ((N_NODES + 31) / 32)                       // 1563 dense blocks
#define NB_KH      ((TOT_E + 127) / 128)                       // 6641 histo blocks

// ---- scratch (device globals; no allocation allowed) ----
__device__ int   g_cnt[N_NODES];
__device__ int   g_off[N_NODES];
__device__ int   g_total;
__device__ int   g_rank[TOT_E];
__device__ int   g_csr[TOT_E];
__device__ __align__(16) __half g_h1h[N_NODES * F1];   // layer1 feats fp16
__device__ __align__(16) float  g_as1[N_NODES * HEADS];
__device__ __align__(16) float  g_ad1[N_NODES * HEADS];
__device__ __align__(16) float  g_out1[N_NODES * F1];  // post-softmax, post-ELU
__device__ __align__(16) float  g_h2[N_NODES * HID];   // layer2 feats fp32
__device__ float g_as2[N_NODES];
__device__ float g_ad2[N_NODES];

__device__ __forceinline__ float warp_sum_f(float v) {
#pragma unroll
    for (int o = 16; o; o >>= 1) v += __shfl_xor_sync(0xffffffffu, v, o);
    return v;
}
__device__ __forceinline__ float lrelu(float e) { return e > 0.f ? e : NEG_SLOPE * e; }
__device__ __forceinline__ float elu(float v)   { return v > 0.f ? v : __expf(v) - 1.f; }

// ============================================================================
// kZ: zero degree counters + global cursor
// ============================================================================
__global__ void kZ() {
    int i = blockIdx.x * blockDim.x + threadIdx.x;
    if (i < N_NODES) g_cnt[i] = 0;
    if (i == 0) g_total = 0;
}

// ============================================================================
// kF: FUSED dense transform + histogram (disjoint state, overlapped on SMs)
// ============================================================================
__global__ void kF(const float* __restrict__ x,  const float* __restrict__ W1,
                   const float* __restrict__ as1, const float* __restrict__ ad1,
                   const int* __restrict__ ei) {
    if (blockIdx.x >= NB_K1) {
        int e = (blockIdx.x - NB_K1) * 128 + threadIdx.x;
        if (e < TOT_E) {
            int dst = (e < E_EDGES) ? ei[E_EDGES + e] : (e - E_EDGES);
            g_rank[e] = atomicAdd(&g_cnt[dst], 1);
        }
        return;
    }

    __shared__ float sW[5 * F1];
    __shared__ float sva[5 * HEADS], svb[5 * HEADS];
    int t = threadIdx.x;
    int n0 = blockIdx.x * 32;

    for (int i = t; i < 5 * F1; i += 128) sW[i] = W1[i];
    if (t < 5 * HEADS) {
        int k = t / HEADS, h = t % HEADS;
        float s = 0.f, d = 0.f;
        for (int c = 0; c < HID; c++) {
            float w = W1[k * F1 + h * HID + c];
            s = fmaf(w, as1[h * HID + c], s);
            d = fmaf(w, ad1[h * HID + c], d);
        }
        sva[t] = s; svb[t] = d;
    }
    __syncthreads();

    for (int j = 0; j < 32; j++) {
        int n = n0 + j;
        if (n >= N_NODES) return;
        float xv[5];
#pragma unroll
        for (int k = 0; k < 5; k++) xv[k] = x[n * 5 + k];
        float h = 0.f;
#pragma unroll
        for (int k = 0; k < 5; k++) h = fmaf(xv[k], sW[k * F1 + t], h);
        g_h1h[n * F1 + t] = __float2half_rn(h);
        if (t < HEADS) {
            float s = 0.f, d = 0.f;
#pragma unroll
            for (int k = 0; k < 5; k++) {
                s = fmaf(xv[k], sva[k * HEADS + t], s);
                d = fmaf(xv[k], svb[k * HEADS + t], d);
            }
            g_as1[n * HEADS + t] = s;
            g_ad1[n * HEADS + t] = d;
        }
    }
}

// ============================================================================
// kOff: block scan + one atomicAdd base claim
// ============================================================================
__global__ void kOff() {
    __shared__ int ws[SCAN_CHUNK / 32 + 1];
    __shared__ int sbase;
    int t = threadIdx.x, b = blockIdx.x;
    int i = b * SCAN_CHUNK + t;
    int lane = t & 31, wid = t >> 5;

    int v = (i < N_NODES) ? g_cnt[i] : 0;
    int x = v;
#pragma unroll
    for (int o = 1; o < 32; o <<= 1) {
        int y = __shfl_up_sync(0xffffffffu, x, o);
        if (lane >= o) x += y;
    }
    if (lane == 31) ws[wid + 1] = x;
    __syncthreads();
    if (t == 0) {
        ws[0] = 0;
        for (int w = 1; w <= SCAN_CHUNK / 32; w++) ws[w] += ws[w - 1];
        sbase = atomicAdd(&g_total, ws[SCAN_CHUNK / 32]);
    }
    __syncthreads();
    int excl = x - v + ws[wid] + sbase;
    if (i < N_NODES) g_off[i] = excl;
}

// ============================================================================
// kC: atomic-free scatter via precomputed ranks
// ============================================================================
__global__ void kC(const int* __restrict__ ei) {
    int e = blockIdx.x * blockDim.x + threadIdx.x;
    if (e >= TOT_E) return;
    int src, dst;
    if (e < E_EDGES) { src = ei[e]; dst = ei[E_EDGES + e]; }
    else             { src = dst = e - E_EDGES; }
    g_csr[g_off[dst] + g_rank[e]] = src;
}

// ============================================================================
// KG1: layer-1 gather. One warp/node, 4-wide, with csr indices SOFTWARE-
// PIPELINED one iteration ahead: removes one of the two serial L2 hops
// (csr -> as/h1) from the per-iteration critical path.
// ============================================================================
__global__ void kG1(const float* __restrict__ b1) {
    int n = (blockIdx.x * blockDim.x + threadIdx.x) >> 5;
    if (n >= N_NODES) return;
    int lane = threadIdx.x & 31;
    int head = lane >> 3;
    int f = lane * 4;

    float adv = g_ad1[n * HEADS + head];
    int beg = g_off[n], cnt = g_cnt[n];

    float a0 = 0.f, a1 = 0.f, a2 = 0.f, a3 = 0.f, den = 0.f;
    int j = 0;
    int s0 = 0, s1 = 0, s2 = 0, s3 = 0;
    if (cnt >= 4) {                       // prologue: prime the index pipeline
        s0 = g_csr[beg + 0];
        s1 = g_csr[beg + 1];
        s2 = g_csr[beg + 2];
        s3 = g_csr[beg + 3];
    }
    for (; j + 3 < cnt; j += 4) {
        int t0 = s0, t1 = s1, t2 = s2, t3 = s3;
        if (j + 7 < cnt) {                // prefetch next quad's indices
            s0 = g_csr[beg + j + 4];
            s1 = g_csr[beg + j + 5];
            s2 = g_csr[beg + j + 6];
            s3 = g_csr[beg + j + 7];
        }
        float e0 = g_as1[t0 * HEADS + head];
        float e1 = g_as1[t1 * HEADS + head];
        float e2 = g_as1[t2 * HEADS + head];
        float e3 = g_as1[t3 * HEADS + head];
        uint2 r0 = *reinterpret_cast<const uint2*>(&g_h1h[t0 * F1 + f]);
        uint2 r1 = *reinterpret_cast<const uint2*>(&g_h1h[t1 * F1 + f]);
        uint2 r2 = *reinterpret_cast<const uint2*>(&g_h1h[t2 * F1 + f]);
        uint2 r3 = *reinterpret_cast<const uint2*>(&g_h1h[t3 * F1 + f]);
        float w0 = __expf(lrelu(e0 + adv));
        float w1 = __expf(lrelu(e1 + adv));
        float w2 = __expf(lrelu(e2 + adv));
        float w3 = __expf(lrelu(e3 + adv));
        float2 pa, pb;
        pa = __half22float2(*reinterpret_cast<__half2*>(&r0.x));
        pb = __half22float2(*reinterpret_cast<__half2*>(&r0.y));
        a0 = fmaf(w0, pa.x, a0); a1 = fmaf(w0, pa.y, a1);
        a2 = fmaf(w0, pb.x, a2); a3 = fmaf(w0, pb.y, a3);
        pa = __half22float2(*reinterpret_cast<__half2*>(&r1.x));
        pb = __half22float2(*reinterpret_cast<__half2*>(&r1.y));
        a0 = fmaf(w1, pa.x, a0); a1 = fmaf(w1, pa.y, a1);
        a2 = fmaf(w1, pb.x, a2); a3 = fmaf(w1, pb.y, a3);
        pa = __half22float2(*reinterpret_cast<__half2*>(&r2.x));
        pb = __half22float2(*reinterpret_cast<__half2*>(&r2.y));
        a0 = fmaf(w2, pa.x, a0); a1 = fmaf(w2, pa.y, a1);
        a2 = fmaf(w2, pb.x, a2); a3 = fmaf(w2, pb.y, a3);
        pa = __half22float2(*reinterpret_cast<__half2*>(&r3.x));
        pb = __half22float2(*reinterpret_cast<__half2*>(&r3.y));
        a0 = fmaf(w3, pa.x, a0); a1 = fmaf(w3, pa.y, a1);
        a2 = fmaf(w3, pb.x, a2); a3 = fmaf(w3, pb.y, a3);
        den += (w0 + w1) + (w2 + w3);
    }
    for (; j < cnt; j++) {
        int t0 = g_csr[beg + j];
        float e0 = g_as1[t0 * HEADS + head];
        uint2 r0 = *reinterpret_cast<const uint2*>(&g_h1h[t0 * F1 + f]);
        float w0 = __expf(lrelu(e0 + adv));
        float2 pa = __half22float2(*reinterpret_cast<__half2*>(&r0.x));
        float2 pb = __half22float2(*reinterpret_cast<__half2*>(&r0.y));
        a0 = fmaf(w0, pa.x, a0); a1 = fmaf(w0, pa.y, a1);
        a2 = fmaf(w0, pb.x, a2); a3 = fmaf(w0, pb.y, a3);
        den += w0;
    }
    float inv = 1.f / den;
    float4 bv = *reinterpret_cast<const float4*>(&b1[f]);
    float4 o;
    o.x = elu(fmaf(a0, inv, bv.x));
    o.y = elu(fmaf(a1, inv, bv.y));
    o.z = elu(fmaf(a2, inv, bv.z));
    o.w = elu(fmaf(a3, inv, bv.w));
    *reinterpret_cast<float4*>(&g_out1[n * F1 + f]) = o;
}

// ============================================================================
// K3: h2 = out1 @ W2, register-blocked 4 nodes/warp
// ============================================================================
__global__ void k3_node2(const float* __restrict__ W2,
                         const float* __restrict__ as2, const float* __restrict__ ad2) {
    __shared__ float sW2[F1 * HID];
    __shared__ float sH[8][4][F1];
    int t = threadIdx.x;
    for (int i = t; i < F1 * HID; i += 256) sW2[i] = W2[i];
    __syncthreads();

    int wid = t >> 5, lane = t & 31;
    int n0 = blockIdx.x * 32 + wid * 4;

#pragma unroll
    for (int j = 0; j < 4; j++) {
        int n = n0 + j;
        if (n < N_NODES) {
#pragma unroll
            for (int q = 0; q < 4; q++)
                sH[wid][j][q * 32 + lane] = g_out1[n * F1 + q * 32 + lane];
        }
    }
    __syncwarp();

    float acc0 = 0.f, acc1 = 0.f, acc2 = 0.f, acc3 = 0.f;
#pragma unroll 4
    for (int k = 0; k < F1; k++) {
        float w = sW2[k * HID + lane];
        acc0 = fmaf(sH[wid][0][k], w, acc0);
        acc1 = fmaf(sH[wid][1][k], w, acc1);
        acc2 = fmaf(sH[wid][2][k], w, acc2);
        acc3 = fmaf(sH[wid][3][k], w, acc3);
    }

    float accs[4] = {acc0, acc1, acc2, acc3};
#pragma unroll
    for (int j = 0; j < 4; j++) {
        int n = n0 + j;
        float acc = accs[j];
        float ps = warp_sum_f(acc * as2[lane]);
        float pd = warp_sum_f(acc * ad2[lane]);
        if (n < N_NODES) {
            g_h2[n * HID + lane] = acc;
            if (lane == 0) { g_as2[n] = ps; g_ad2[n] = pd; }
        }
    }
}

// ============================================================================
// KG2: layer-2 gather + fused MLP head. One warp/node, 4-wide, csr pipelined.
// ============================================================================
__global__ void kG2(const float* __restrict__ b2,  const float* __restrict__ Wc1,
                    const float* __restrict__ bc1, const float* __restrict__ Wc2,
                    const float* __restrict__ bc2, float* __restrict__ out) {
    __shared__ float sv[8][HID];
    int n = (blockIdx.x * blockDim.x + threadIdx.x) >> 5;
    if (n >= N_NODES) return;
    int lane = threadIdx.x & 31;
    int wid = (threadIdx.x >> 5) & 7;

    float adv = g_ad2[n];
    int beg = g_off[n], cnt = g_cnt[n];

    float acc = 0.f, den = 0.f;
    int j = 0;
    int s0 = 0, s1 = 0, s2 = 0, s3 = 0;
    if (cnt >= 4) {
        s0 = g_csr[beg + 0];
        s1 = g_csr[beg + 1];
        s2 = g_csr[beg + 2];
        s3 = g_csr[beg + 3];
    }
    for (; j + 3 < cnt; j += 4) {
        int t0 = s0, t1 = s1, t2 = s2, t3 = s3;
        if (j + 7 < cnt) {
            s0 = g_csr[beg + j + 4];
            s1 = g_csr[beg + j + 5];
            s2 = g_csr[beg + j + 6];
            s3 = g_csr[beg + j + 7];
        }
        float e0 = g_as2[t0];
        float e1 = g_as2[t1];
        float e2 = g_as2[t2];
        float e3 = g_as2[t3];
        float h0 = g_h2[t0 * HID + lane];
        float h1 = g_h2[t1 * HID + lane];
        float h2v = g_h2[t2 * HID + lane];
        float h3 = g_h2[t3 * HID + lane];
        float w0 = __expf(lrelu(e0 + adv));
        float w1 = __expf(lrelu(e1 + adv));
        float w2 = __expf(lrelu(e2 + adv));
        float w3 = __expf(lrelu(e3 + adv));
        acc = fmaf(w0, h0, acc);
        acc = fmaf(w1, h1, acc);
        acc = fmaf(w2, h2v, acc);
        acc = fmaf(w3, h3, acc);
        den += (w0 + w1) + (w2 + w3);
    }
    for (; j < cnt; j++) {
        int t0 = g_csr[beg + j];
        float w0 = __expf(lrelu(g_as2[t0] + adv));
        acc = fmaf(w0, g_h2[t0 * HID + lane], acc);
        den += w0;
    }
    float v = elu(acc / den + b2[lane]);
    sv[wid][lane] = v;
    __syncwarp();

    float tj = 0.f;
    if (lane < 16) {
        tj = bc1[lane];
#pragma unroll
        for (int c = 0; c < HID; c++) tj = fmaf(sv[wid][c], Wc1[c * 16 + lane], tj);
        tj = fmaxf(tj, 0.f) * Wc2[lane];
    }
#pragma unroll
    for (int o = 16; o; o >>= 1) tj += __shfl_xor_sync(0xffffffffu, tj, o);
    if (lane == 0) out[n] = tj + bc2[0];
}

// ============================================================================
extern "C" void kernel_launch(void* const* d_in, const int* in_sizes, int n_in,
                              void* d_out, int out_size) {
    const float* x   = (const float*)d_in[0];
    const int*   ei  = (const int*)  d_in[1];
    const float* W1  = (const float*)d_in[2];
    const float* as1 = (const float*)d_in[3];
    const float* ad1 = (const float*)d_in[4];
    const float* b1  = (const float*)d_in[5];
    const float* W2  = (const float*)d_in[6];
    const float* as2 = (const float*)d_in[7];
    const float* ad2 = (const float*)d_in[8];
    const float* b2  = (const float*)d_in[9];
    const float* Wc1 = (const float*)d_in[10];
    const float* bc1 = (const float*)d_in[11];
    const float* Wc2 = (const float*)d_in[12];
    const float* bc2 = (const float*)d_in[13];
    float* out = (float*)d_out;

    kZ  <<<(N_NODES + 255) / 256, 256>>>();
    kF  <<<NB_K1 + NB_KH, 128>>>(x, W1, as1, ad1, ei);         // k1 ∥ kH overlapped
    kOff<<<NB_SCAN, SCAN_CHUNK>>>();
    kC  <<<(TOT_E + 255) / 256, 256>>>(ei);
    kG1 <<<(N_NODES * 32 + 255) / 256, 256>>>(b1);             // pipelined gather
    k3_node2<<<(N_NODES + 31) / 32, 256>>>(W2, as2, ad2);
    kG2 <<<(N_NODES * 32 + 255) / 256, 256>>>(b2, Wc1, bc1, Wc2, bc2, out);
}